// round 1
// baseline (speedup 1.0000x reference)
#include <cuda_runtime.h>
#include <math.h>

#define S_LEN 2048
#define B_SZ  32
#define D_SZ  512
#define KCONV 147
#define PADC  73
#define NS    32
#define CHUNK (S_LEN / NS)   // 64 rows of s per block

// ---------------- scratch (static device globals; no allocs) ----------------
__device__ float g_attp[2][B_SZ * D_SZ];    // GEMM k-split partials
__device__ float g_ns [B_SZ * D_SZ];        // normalized attended state
__device__ float g_adj[B_SZ * S_LEN];       // relu(conv(prev)+cb)
__device__ float g_w  [B_SZ * S_LEN];       // cosine weights
__device__ float g_pm [B_SZ * NS];          // per-split running max
__device__ float g_pz [B_SZ * NS];          // per-split csum
__device__ float g_pacc[B_SZ * NS * D_SZ];  // per-split weighted-sum partials

// ---------------- kernel 1: attended = state @ W^T (k-split) ----------------
// grid (64, 2): blockIdx.x -> 8 d's, blockIdx.y -> k half. 256 threads.
__global__ __launch_bounds__(256) void k_gemm(const float* __restrict__ state,
                                              const float* __restrict__ W) {
    __shared__ float st[256][33];   // k-chunk x batch (padded, conflict-free)
    __shared__ float ws[8][256];    // d x k-chunk
    const int tid  = threadIdx.x;
    const int lane = tid & 31;      // batch index
    const int wid  = tid >> 5;      // which of 8 d's
    const int k0   = blockIdx.y * 256;
    const int d    = blockIdx.x * 8 + wid;

    for (int i = tid; i < 32 * 256; i += 256) {
        int b = i >> 8, kk = i & 255;
        st[kk][b] = state[b * D_SZ + k0 + kk];
    }
    for (int i = tid; i < 8 * 256; i += 256) {
        int dd = i >> 8, kk = i & 255;
        ws[dd][kk] = W[(blockIdx.x * 8 + dd) * D_SZ + k0 + kk];
    }
    __syncthreads();

    float acc = 0.f;
#pragma unroll 8
    for (int kk = 0; kk < 256; kk++)
        acc = fmaf(st[kk][lane], ws[wid][kk], acc);

    g_attp[blockIdx.y][lane * D_SZ + d] = acc;
}

// ---------------- kernel 2: ns = normalize(attended + b_att) ----------------
// grid 32 (one per batch), 128 threads, float4 lanes
__global__ __launch_bounds__(128) void k_ns(const float* __restrict__ b_att) {
    __shared__ float red[4];
    __shared__ float inv_s;
    const int b = blockIdx.x, tid = threadIdx.x;
    const int lane = tid & 31, wid = tid >> 5;

    float4 a0 = reinterpret_cast<const float4*>(g_attp[0])[b * 128 + tid];
    float4 a1 = reinterpret_cast<const float4*>(g_attp[1])[b * 128 + tid];
    float4 bb = reinterpret_cast<const float4*>(b_att)[tid];
    float4 a;
    a.x = a0.x + a1.x + bb.x;  a.y = a0.y + a1.y + bb.y;
    a.z = a0.z + a1.z + bb.z;  a.w = a0.w + a1.w + bb.w;

    float ss = a.x * a.x + a.y * a.y + a.z * a.z + a.w * a.w;
#pragma unroll
    for (int o = 16; o; o >>= 1) ss += __shfl_down_sync(0xffffffffu, ss, o);
    if (lane == 0) red[wid] = ss;
    __syncthreads();
    if (tid == 0) {
        float t = red[0] + red[1] + red[2] + red[3];
        float n = sqrtf(t);
        n = (n != 0.f) ? n : 1e-10f;
        inv_s = 1.f / n;
    }
    __syncthreads();
    float inv = inv_s;
    float4 o4; o4.x = a.x * inv; o4.y = a.y * inv; o4.z = a.z * inv; o4.w = a.w * inv;
    reinterpret_cast<float4*>(g_ns)[b * 128 + tid] = o4;
}

// ---------------- kernel 3: conv1d smoothing + relu ----------------
// grid (8, 32): 256-wide s chunk per block, one batch per blockIdx.y
__global__ __launch_bounds__(256) void k_conv(const float* __restrict__ prev,
                                              const float* __restrict__ cw,
                                              const float* __restrict__ cb) {
    __shared__ float sp[256 + 2 * PADC];
    const int b = blockIdx.y, c0 = blockIdx.x * 256, tid = threadIdx.x;

    for (int i = tid; i < 256 + 2 * PADC; i += 256) {
        int s = c0 + i - PADC;
        sp[i] = (s >= 0 && s < S_LEN) ? prev[b * S_LEN + s] : 0.f;
    }
    __syncthreads();

    float acc = 0.f;
#pragma unroll 7
    for (int j = 0; j < KCONV; j++)
        acc = fmaf(sp[tid + j], __ldg(&cw[j]), acc);

    g_adj[b * S_LEN + c0 + tid] = fmaxf(acc + __ldg(cb), 0.f);
}

// ---------------- kernel 4: fused weights + online weighted-sum ----------------
// grid (NS, B): one s-split per blockIdx.x, one batch per blockIdx.y. 128 thr.
__global__ __launch_bounds__(128) void k_main(const float* __restrict__ enc) {
    __shared__ float rdot[4], rss[4];
    __shared__ float wsm;
    const int b = blockIdx.y, sp = blockIdx.x;
    const int tid = threadIdx.x, lane = tid & 31, wid = tid >> 5;
    const int s0 = sp * CHUNK;

    const float4* enc4 = reinterpret_cast<const float4*>(enc);
    float4 n4 = reinterpret_cast<const float4*>(g_ns)[b * 128 + tid];

    float4 acc = make_float4(0.f, 0.f, 0.f, 0.f);
    float m = -INFINITY, csum = 0.f;

    float4 e = enc4[((long)s0 * B_SZ + b) * 128 + tid];

#pragma unroll 4
    for (int i = 0; i < CHUNK; i++) {
        const int s = s0 + i;
        // prefetch next row to overlap with the reduction chain
        float4 en = make_float4(0.f, 0.f, 0.f, 0.f);
        if (i + 1 < CHUNK)
            en = enc4[((long)(s + 1) * B_SZ + b) * 128 + tid];

        float dot = e.x * n4.x + e.y * n4.y + e.z * n4.z + e.w * n4.w;
        float ss  = e.x * e.x  + e.y * e.y  + e.z * e.z  + e.w * e.w;
#pragma unroll
        for (int o = 16; o; o >>= 1) {
            dot += __shfl_down_sync(0xffffffffu, dot, o);
            ss  += __shfl_down_sync(0xffffffffu, ss,  o);
        }
        if (lane == 0) { rdot[wid] = dot; rss[wid] = ss; }
        __syncthreads();
        if (tid == 0) {
            float D_ = rdot[0] + rdot[1] + rdot[2] + rdot[3];
            float S_ = rss[0]  + rss[1]  + rss[2]  + rss[3];
            float n = sqrtf(S_);
            n = (n != 0.f) ? n : 1e-10f;
            float w = D_ / n;
            wsm = w;
            g_w[b * S_LEN + s] = w;
        }
        __syncthreads();
        float w = wsm;

        float a  = __ldg(&g_adj[b * S_LEN + s]);
        float nm = fmaxf(m, w);
        float sc = __expf(m - nm);           // 0 on first iter (m=-inf)
        float c  = a * __expf(w - nm);
        csum = csum * sc + c;
        acc.x = fmaf(c, e.x, acc.x * sc);
        acc.y = fmaf(c, e.y, acc.y * sc);
        acc.z = fmaf(c, e.z, acc.z * sc);
        acc.w = fmaf(c, e.w, acc.w * sc);
        m = nm;
        e = en;
    }

    reinterpret_cast<float4*>(g_pacc)[(b * NS + sp) * 128 + tid] = acc;
    if (tid == 0) {
        g_pm[b * NS + sp] = m;
        g_pz[b * NS + sp] = csum;
    }
}

// ---------------- kernel 5: combine partials, write outputs ----------------
// grid 32 (batch), 256 threads. out = [applied (B*D) | norm_w (B*S)]
__global__ __launch_bounds__(256) void k_final(float* __restrict__ out) {
    __shared__ float ef[NS];
    __shared__ float Msh, invZsh;
    const int b = blockIdx.x, tid = threadIdx.x;

    if (tid == 0) {
        float M = -INFINITY;
#pragma unroll
        for (int p = 0; p < NS; p++) M = fmaxf(M, g_pm[b * NS + p]);
        float Z = 0.f;
#pragma unroll
        for (int p = 0; p < NS; p++) {
            float e_ = __expf(g_pm[b * NS + p] - M);
            ef[p] = e_;
            Z = fmaf(g_pz[b * NS + p], e_, Z);
        }
        Msh = M;
        invZsh = 1.f / Z;
    }
    __syncthreads();
    const float M = Msh, invZ = invZsh;

    // applied: 256 threads x float2 covers 512 floats
    float2 s2 = make_float2(0.f, 0.f);
    const float2* pacc2 = reinterpret_cast<const float2*>(g_pacc);
#pragma unroll
    for (int p = 0; p < NS; p++) {
        float2 v = pacc2[(b * NS + p) * 256 + tid];
        s2.x = fmaf(v.x, ef[p], s2.x);
        s2.y = fmaf(v.y, ef[p], s2.y);
    }
    float2 o2; o2.x = s2.x * invZ; o2.y = s2.y * invZ;
    reinterpret_cast<float2*>(out)[b * 256 + tid] = o2;

    // norm_w
    for (int s = tid; s < S_LEN; s += 256) {
        float v = g_adj[b * S_LEN + s] * __expf(g_w[b * S_LEN + s] - M) * invZ;
        out[B_SZ * D_SZ + b * S_LEN + s] = v;
    }
}

// ---------------- launch ----------------
extern "C" void kernel_launch(void* const* d_in, const int* in_sizes, int n_in,
                              void* d_out, int out_size) {
    const float* enc   = (const float*)d_in[0];  // [S,B,D]
    const float* state = (const float*)d_in[1];  // [B,D]
    const float* prev  = (const float*)d_in[2];  // [B,S]
    const float* W     = (const float*)d_in[3];  // [D,D]
    const float* batt  = (const float*)d_in[4];  // [D]
    const float* cw    = (const float*)d_in[5];  // [1,1,K]
    const float* cb    = (const float*)d_in[6];  // [1]
    float* out = (float*)d_out;

    k_gemm <<<dim3(64, 2),     256>>>(state, W);
    k_ns   <<<32,              128>>>(batt);
    k_conv <<<dim3(8, B_SZ),   256>>>(prev, cw, cb);
    k_main <<<dim3(NS, B_SZ),  128>>>(enc);
    k_final<<<B_SZ,            256>>>(out);
}

// round 2
// speedup vs baseline: 1.4246x; 1.4246x over previous
#include <cuda_runtime.h>
#include <math.h>

#define S_LEN 2048
#define B_SZ  32
#define D_SZ  512
#define KCONV 147
#define PADC  73
#define NS    32                 // s-splits for k_main
#define ROWS_PB (S_LEN / NS)     // 64 rows per block
#define ROWS_PW (ROWS_PB / 8)    // 8 rows per warp

// ---------------- scratch ----------------
__device__ float g_attp[2][B_SZ * D_SZ];     // GEMM k-split partials
__device__ float g_adj[B_SZ * S_LEN];        // relu(conv(prev)+cb)
__device__ float g_c  [B_SZ * S_LEN];        // adj * exp(w)  (unnormalized weight)
__device__ float g_pz [B_SZ * NS];           // per-split sum of c
__device__ float g_pacc[B_SZ * NS * D_SZ];   // per-split weighted-sum partials

// ---------------- kernel 1: GEMM (blocks 0..127) + conv (blocks 128..383) ----
__global__ __launch_bounds__(256) void k_pre(const float* __restrict__ state,
                                             const float* __restrict__ W,
                                             const float* __restrict__ prev,
                                             const float* __restrict__ cw,
                                             const float* __restrict__ cb) {
    const int tid = threadIdx.x;
    if (blockIdx.x < 128) {
        // ---- GEMM: attended = state @ W^T (k-split) ----
        __shared__ float st[256][33];
        __shared__ float ws[8][256];
        const int gx = blockIdx.x & 63;
        const int gy = blockIdx.x >> 6;
        const int lane = tid & 31;      // batch
        const int wid  = tid >> 5;      // which of 8 d's
        const int k0   = gy * 256;
        const int d    = gx * 8 + wid;

        for (int i = tid; i < 32 * 256; i += 256) {
            int b = i >> 8, kk = i & 255;
            st[kk][b] = state[b * D_SZ + k0 + kk];
        }
        for (int i = tid; i < 8 * 256; i += 256) {
            int dd = i >> 8, kk = i & 255;
            ws[dd][kk] = W[(gx * 8 + dd) * D_SZ + k0 + kk];
        }
        __syncthreads();

        float acc = 0.f;
#pragma unroll 8
        for (int kk = 0; kk < 256; kk++)
            acc = fmaf(st[kk][lane], ws[wid][kk], acc);

        g_attp[gy][lane * D_SZ + d] = acc;
    } else {
        // ---- conv1d smoothing + relu ----
        __shared__ float sp[256 + 2 * PADC];
        const int idx = blockIdx.x - 128;
        const int b = idx & 31, c0 = (idx >> 5) * 256;

        for (int i = tid; i < 256 + 2 * PADC; i += 256) {
            int s = c0 + i - PADC;
            sp[i] = (s >= 0 && s < S_LEN) ? prev[b * S_LEN + s] : 0.f;
        }
        __syncthreads();

        float acc = 0.f;
#pragma unroll 7
        for (int j = 0; j < KCONV; j++)
            acc = fmaf(sp[tid + j], __ldg(&cw[j]), acc);

        g_adj[b * S_LEN + c0 + tid] = fmaxf(acc + __ldg(cb), 0.f);
    }
}

// ---------------- kernel 2: fused ns + weights + weighted-sum ----------------
// grid (B_SZ, NS): b = blockIdx.x (fast, locality in s-region), sp = blockIdx.y
// 256 threads = 8 warps; each warp owns full D row, 8 rows serially; no
// __syncthreads in the hot loop (warp-level shfl_xor reduces only).
__global__ __launch_bounds__(256) void k_main(const float* __restrict__ enc,
                                              const float* __restrict__ b_att) {
    const int b   = blockIdx.x;
    const int sp  = blockIdx.y;
    const int tid = threadIdx.x, lane = tid & 31, w = tid >> 5;

    const float4* enc4 = reinterpret_cast<const float4*>(enc);
    const float4* at0  = reinterpret_cast<const float4*>(g_attp[0]);
    const float4* at1  = reinterpret_cast<const float4*>(g_attp[1]);
    const float4* ba4  = reinterpret_cast<const float4*>(b_att);

    // ---- build normalized attended state (per warp, redundantly; lanes x 4 float4 cover D) ----
    float4 n0, n1, n2, n3;
    {
        float4 a0, a1, a2, a3, t;
#define LD_AT(q, dst) \
        dst = at0[b * 128 + (q) * 32 + lane]; \
        t   = at1[b * 128 + (q) * 32 + lane]; \
        dst.x += t.x; dst.y += t.y; dst.z += t.z; dst.w += t.w; \
        t   = ba4[(q) * 32 + lane]; \
        dst.x += t.x; dst.y += t.y; dst.z += t.z; dst.w += t.w;
        LD_AT(0, a0) LD_AT(1, a1) LD_AT(2, a2) LD_AT(3, a3)
#undef LD_AT
        float ss = a0.x*a0.x + a0.y*a0.y + a0.z*a0.z + a0.w*a0.w
                 + a1.x*a1.x + a1.y*a1.y + a1.z*a1.z + a1.w*a1.w
                 + a2.x*a2.x + a2.y*a2.y + a2.z*a2.z + a2.w*a2.w
                 + a3.x*a3.x + a3.y*a3.y + a3.z*a3.z + a3.w*a3.w;
#pragma unroll
        for (int o = 16; o; o >>= 1) ss += __shfl_xor_sync(0xffffffffu, ss, o);
        float inv = (ss > 0.f) ? rsqrtf(ss) : 1e10f;
        n0.x=a0.x*inv; n0.y=a0.y*inv; n0.z=a0.z*inv; n0.w=a0.w*inv;
        n1.x=a1.x*inv; n1.y=a1.y*inv; n1.z=a1.z*inv; n1.w=a1.w*inv;
        n2.x=a2.x*inv; n2.y=a2.y*inv; n2.z=a2.z*inv; n2.w=a2.w*inv;
        n3.x=a3.x*inv; n3.y=a3.y*inv; n3.z=a3.z*inv; n3.w=a3.w*inv;
    }

    const int sbase = sp * ROWS_PB + w * ROWS_PW;

    float4 acc0 = make_float4(0,0,0,0), acc1 = acc0, acc2 = acc0, acc3 = acc0;
    float csum = 0.f;

    // preload first row
    long rb = ((long)sbase * B_SZ + b) * 128;
    float4 e0 = enc4[rb + 0*32 + lane];
    float4 e1 = enc4[rb + 1*32 + lane];
    float4 e2 = enc4[rb + 2*32 + lane];
    float4 e3 = enc4[rb + 3*32 + lane];

#pragma unroll
    for (int i = 0; i < ROWS_PW; i++) {
        const int s = sbase + i;
        float4 f0, f1, f2, f3;
        if (i + 1 < ROWS_PW) {
            long nb = ((long)(s + 1) * B_SZ + b) * 128;
            f0 = enc4[nb + 0*32 + lane];
            f1 = enc4[nb + 1*32 + lane];
            f2 = enc4[nb + 2*32 + lane];
            f3 = enc4[nb + 3*32 + lane];
        }
        float dot = e0.x*n0.x + e0.y*n0.y + e0.z*n0.z + e0.w*n0.w
                  + e1.x*n1.x + e1.y*n1.y + e1.z*n1.z + e1.w*n1.w
                  + e2.x*n2.x + e2.y*n2.y + e2.z*n2.z + e2.w*n2.w
                  + e3.x*n3.x + e3.y*n3.y + e3.z*n3.z + e3.w*n3.w;
        float ss  = e0.x*e0.x + e0.y*e0.y + e0.z*e0.z + e0.w*e0.w
                  + e1.x*e1.x + e1.y*e1.y + e1.z*e1.z + e1.w*e1.w
                  + e2.x*e2.x + e2.y*e2.y + e2.z*e2.z + e2.w*e2.w
                  + e3.x*e3.x + e3.y*e3.y + e3.z*e3.z + e3.w*e3.w;
#pragma unroll
        for (int o = 16; o; o >>= 1) {
            dot += __shfl_xor_sync(0xffffffffu, dot, o);
            ss  += __shfl_xor_sync(0xffffffffu, ss,  o);
        }
        // cosine weight; |wt| <= 1 so exp(wt) is always safe (no max trick needed)
        float wt = dot * ((ss > 0.f) ? rsqrtf(ss) : 1e10f);
        float c  = __ldg(&g_adj[b * S_LEN + s]) * __expf(wt);
        if (lane == 0) g_c[b * S_LEN + s] = c;
        csum += c;
        acc0.x = fmaf(c, e0.x, acc0.x); acc0.y = fmaf(c, e0.y, acc0.y);
        acc0.z = fmaf(c, e0.z, acc0.z); acc0.w = fmaf(c, e0.w, acc0.w);
        acc1.x = fmaf(c, e1.x, acc1.x); acc1.y = fmaf(c, e1.y, acc1.y);
        acc1.z = fmaf(c, e1.z, acc1.z); acc1.w = fmaf(c, e1.w, acc1.w);
        acc2.x = fmaf(c, e2.x, acc2.x); acc2.y = fmaf(c, e2.y, acc2.y);
        acc2.z = fmaf(c, e2.z, acc2.z); acc2.w = fmaf(c, e2.w, acc2.w);
        acc3.x = fmaf(c, e3.x, acc3.x); acc3.y = fmaf(c, e3.y, acc3.y);
        acc3.z = fmaf(c, e3.z, acc3.z); acc3.w = fmaf(c, e3.w, acc3.w);
        e0 = f0; e1 = f1; e2 = f2; e3 = f3;
    }

    // ---- block combine (one barrier total) ----
    __shared__ float4 sacc[8][128];
    __shared__ float  scs[8];
    sacc[w][0*32 + lane] = acc0;
    sacc[w][1*32 + lane] = acc1;
    sacc[w][2*32 + lane] = acc2;
    sacc[w][3*32 + lane] = acc3;
    if (lane == 0) scs[w] = csum;
    __syncthreads();

    if (tid < 128) {
        float4 v = sacc[0][tid];
#pragma unroll
        for (int p = 1; p < 8; p++) {
            float4 u = sacc[p][tid];
            v.x += u.x; v.y += u.y; v.z += u.z; v.w += u.w;
        }
        reinterpret_cast<float4*>(g_pacc)[(b * NS + sp) * 128 + tid] = v;
    }
    if (tid == 0) {
        float z = 0.f;
#pragma unroll
        for (int p = 0; p < 8; p++) z += scs[p];
        g_pz[b * NS + sp] = z;
    }
}

// ---------------- kernel 3: combine partials, write outputs ----------------
__global__ __launch_bounds__(256) void k_final(float* __restrict__ out) {
    __shared__ float invZsh;
    const int b = blockIdx.x, tid = threadIdx.x;

    if (tid == 0) {
        float Z = 0.f;
#pragma unroll
        for (int p = 0; p < NS; p++) Z += g_pz[b * NS + p];
        invZsh = 1.f / Z;
    }
    __syncthreads();
    const float invZ = invZsh;

    // applied: 256 threads x float2 = 512 floats
    float2 s2 = make_float2(0.f, 0.f);
    const float2* pacc2 = reinterpret_cast<const float2*>(g_pacc);
#pragma unroll
    for (int p = 0; p < NS; p++) {
        float2 v = pacc2[(b * NS + p) * 256 + tid];
        s2.x += v.x; s2.y += v.y;
    }
    float2 o2; o2.x = s2.x * invZ; o2.y = s2.y * invZ;
    reinterpret_cast<float2*>(out)[b * 256 + tid] = o2;

    // norm_w
    for (int s = tid; s < S_LEN; s += 256)
        out[B_SZ * D_SZ + b * S_LEN + s] = g_c[b * S_LEN + s] * invZ;
}

// ---------------- launch ----------------
extern "C" void kernel_launch(void* const* d_in, const int* in_sizes, int n_in,
                              void* d_out, int out_size) {
    const float* enc   = (const float*)d_in[0];
    const float* state = (const float*)d_in[1];
    const float* prev  = (const float*)d_in[2];
    const float* W     = (const float*)d_in[3];
    const float* batt  = (const float*)d_in[4];
    const float* cw    = (const float*)d_in[5];
    const float* cb    = (const float*)d_in[6];
    float* out = (float*)d_out;

    k_pre  <<<384,              256>>>(state, W, prev, cw, cb);
    k_main <<<dim3(B_SZ, NS),   256>>>(enc, batt);
    k_final<<<B_SZ,             256>>>(out);
}